// round 12
// baseline (speedup 1.0000x reference)
#include <cuda_runtime.h>
#include <cuda_fp16.h>
#include <math.h>
#include <cstdint>

typedef unsigned long long ull;

// ---------------- problem constants ----------------
#define BATCH 8
#define HWP   65536
#define G2    128
#define DD    9

// smem row stride in bytes (MUST be multiple of 16 for ldmatrix/float4)
#define RS 80

// ---------------- scratch ----------------------------------------------------
__device__ __align__(16) float d_xemb[BATCH * 64 * HWP];
__device__ __align__(16) float d_yemb[BATCH * 64 * HWP];
__device__ __align__(16) float d_h   [BATCH * G2 * HWP];
__device__ __align__(16) float d_gates[BATCH * DD * HWP];
__device__ __align__(16) float d_r0  [BATCH * HWP];
__device__ __align__(16) float d_r1  [BATCH * HWP];
__device__ __align__(16) __half d_W1h[72 * 4096];   // [ch][co][kk] fp16
__device__ __align__(16) __half d_W2h[36 * 512];    // [ch][co16][kk] fp16

// ---------------- helpers ----------------------------------------------------
__device__ __forceinline__ uint32_t smem_u32(const void* p) {
    uint32_t a;
    asm("{ .reg .u64 t; cvta.to.shared.u64 t, %1; cvt.u32.u64 %0, t; }" : "=r"(a) : "l"(p));
    return a;
}
__device__ __forceinline__ ull ffma2(ull a, ull b, ull c) {
    ull d; asm("fma.rn.f32x2 %0, %1, %2, %3;" : "=l"(d) : "l"(a), "l"(b), "l"(c)); return d;
}
__device__ __forceinline__ ull pack2(float a) {
    ull d; asm("mov.b64 %0, {%1, %1};" : "=l"(d) : "f"(a)); return d;
}
__device__ __forceinline__ void ldsm_x4(uint32_t* r, uint32_t addr) {
    asm volatile("ldmatrix.sync.aligned.m8n8.x4.shared.b16 {%0,%1,%2,%3}, [%4];"
                 : "=r"(r[0]), "=r"(r[1]), "=r"(r[2]), "=r"(r[3]) : "r"(addr));
}
__device__ __forceinline__ void mma_f16(float* d,
                                        const uint32_t* a, uint32_t b0, uint32_t b1) {
    asm volatile("mma.sync.aligned.m16n8k16.row.col.f32.f16.f16.f32 "
                 "{%0,%1,%2,%3}, {%4,%5,%6,%7}, {%8,%9}, {%0,%1,%2,%3};"
                 : "+f"(d[0]), "+f"(d[1]), "+f"(d[2]), "+f"(d[3])
                 : "r"(a[0]), "r"(a[1]), "r"(a[2]), "r"(a[3]), "r"(b0), "r"(b1));
}

// ---------------- 0a: Wg1 -> fp16 tiles [ch][co][kk] ------------------------
// k = ch*32+kk ; tap = ch>>3 ; ci256 = (ch&7)*32 + kk
__global__ void prep_w1(const float* __restrict__ Wg1) {
    int i = blockIdx.x * 256 + threadIdx.x;
    if (i >= 72 * 4096) return;
    int ch = i >> 12;
    int r  = i & 4095;
    int co = r >> 5;
    int kk = r & 31;
    int tap   = ch >> 3;
    int ci256 = ((ch & 7) << 5) + kk;
    d_W1h[i] = __float2half(Wg1[co * 2304 + ci256 * 9 + tap]);
}

// ---------------- 0b: Wg2 -> fp16 tiles [ch][co16][kk] ----------------------
// k = tap*128 + ci ; tap = ch>>2 ; ci = (ch&3)*32 + kk ; co padded to 16
__global__ void prep_w2(const float* __restrict__ Wg2) {
    int i = blockIdx.x * 256 + threadIdx.x;
    if (i >= 36 * 512) return;
    int ch = i >> 9;
    int r  = i & 511;
    int co = r >> 5;
    int kk = r & 31;
    int tap = ch >> 2;
    int ci  = ((ch & 3) << 5) + kk;
    float w = (co < 9) ? Wg2[co * 1152 + ci * 9 + tap] : 0.f;
    d_W2h[i] = __float2half(w);
}

// ---------------- 1: 1x1 conv + L2 normalize (f32x2) ------------------------
__global__ void __launch_bounds__(256)
embed_kernel(const float* __restrict__ in, const float* __restrict__ w, int which) {
    __shared__ __align__(8) float ws[64 * 64];     // [ci][e]
    int tid = threadIdx.x;
    for (int i = tid; i < 4096; i += 256) {
        int e = i >> 6, ci = i & 63;
        ws[ci * 64 + e] = w[i];
    }
    __syncthreads();
    int pix = blockIdx.x * 256 + tid;
    int b = pix >> 16, hw = pix & 65535;
    const float* ip = in + (b << 22) + hw;

    ull acc2[32];
#pragma unroll
    for (int j = 0; j < 32; j++) acc2[j] = 0ULL;
#pragma unroll 4
    for (int ci = 0; ci < 64; ci++) {
        float v = ip[ci << 16];
        ull vp = pack2(v);
        const ull* wp = (const ull*)(ws + (ci << 6));
#pragma unroll
        for (int j = 0; j < 32; j++) acc2[j] = ffma2(vp, wp[j], acc2[j]);
    }
    ull ss2 = 0;
#pragma unroll
    for (int j = 0; j < 32; j++) ss2 = ffma2(acc2[j], acc2[j], ss2);
    float ss = __uint_as_float((unsigned)ss2) + __uint_as_float((unsigned)(ss2 >> 32));
    float inv = 1.f / (sqrtf(ss) + 1e-6f);
    float* op = (which ? d_yemb : d_xemb) + (b << 22) + hw;
#pragma unroll
    for (int j = 0; j < 32; j++) {
        op[(2 * j) << 16]     = __uint_as_float((unsigned)acc2[j]) * inv;
        op[(2 * j + 1) << 16] = __uint_as_float((unsigned)(acc2[j] >> 32)) * inv;
    }
}

// ---------------- 2: r0 -----------------------------------------------------
__global__ void __launch_bounds__(256) r0_kernel() {
    int pix = blockIdx.x * 256 + threadIdx.x;
    int b = pix >> 16, hw = pix & 65535;
    const float* xp = d_xemb + (b << 22) + hw;
    const float* yp = d_yemb + (b << 22) + hw;
    float s = 0.f;
#pragma unroll 8
    for (int e = 0; e < 64; e++) s = fmaf(xp[e << 16], yp[e << 16], s);
    d_r0[pix] = (s + 1.f) * 0.5f;
}

// ---------------- 3: conv1 (3x3 256->128) fp16 mma implicit GEMM ------------
// CTA 128co x 128px ; K=2304 in 72 chunks of 32.
// smem rows: 64B fp16 data + 16B pad (stride 80B, 16B-aligned rows).
__global__ void __launch_bounds__(256, 1)
conv1_mma(const float* __restrict__ bn_g, const float* __restrict__ bn_b,
          const float* __restrict__ bn_m, const float* __restrict__ bn_v) {
    __shared__ __align__(16) char As[2][128 * RS];
    __shared__ __align__(16) char Bs[2][128 * RS];
    __shared__ float ssc[128], sbi[128];

    const int tid = threadIdx.x;
    const int lid = tid & 31;
    const int wid = tid >> 5;
    const int wm = wid >> 2;            // 0..1 (m block of 64)
    const int wn = wid & 3;             // 0..3 (n block of 32)
    const int b  = blockIdx.y;
    const int y  = blockIdx.x >> 1;
    const int x0 = (blockIdx.x & 1) << 7;
    const int col  = tid & 127;         // pixel for B fill
    const int half = tid >> 7;          // k-half for B fill

    if (tid < 128) {
        float iv = rsqrtf(bn_v[tid] + 1e-5f);
        float sc = bn_g[tid] * iv;
        ssc[tid] = sc;
        sbi[tid] = bn_b[tid] - bn_m[tid] * sc;
    }

    float acc[4][4][4];
#pragma unroll
    for (int i = 0; i < 4; i++)
#pragma unroll
        for (int j = 0; j < 4; j++)
#pragma unroll
            for (int c = 0; c < 4; c++) acc[i][j][c] = 0.f;

    float4 pa[2];
    float  pv[16];

    auto gload = [&](int ch) {
        const float4* asrc = (const float4*)(d_W1h + ch * 4096);
        pa[0] = asrc[tid];
        pa[1] = asrc[tid + 256];
        int tap = ch >> 3;
        int ci0 = (ch & 7) << 5;
        int grp = ci0 >> 6;
        int c0  = ci0 & 63;
        int dy = tap / 3 - 1, dx = tap % 3 - 1;
        int yy = y + dy;
        int xx = x0 + dx + col;
        bool inb = ((unsigned)yy < 256u) && ((unsigned)xx < 256u);
        long base = ((long)((b << 6) + c0 + (half << 4)) << 16) + yy * 256 + xx;
        const float* xp = d_xemb + base;
        const float* yp = d_yemb + base;
#pragma unroll
        for (int i = 0; i < 16; i++) {
            float vx = 0.f, vy = 0.f;
            if (grp != 1 && inb) vx = xp[i << 16];
            if (grp != 0 && inb) vy = yp[i << 16];
            float v;
            if      (grp == 0) v = vx;
            else if (grp == 1) v = vy;
            else if (grp == 2) v = fabsf(vx - vy);
            else               v = vx * vy;
            pv[i] = v;
        }
    };

    auto sstore = [&](int buf) {
        // A: float4 g covers (co = g>>2, 16B quarter = g&3)
        *(float4*)(As[buf] + (tid >> 2) * RS + (tid & 3) * 16) = pa[0];
        {
            int t1 = tid + 256;
            *(float4*)(As[buf] + (t1 >> 2) * RS + (t1 & 3) * 16) = pa[1];
        }
        char* bd = Bs[buf] + col * RS + half * 32;
#pragma unroll
        for (int j = 0; j < 8; j++)
            *(__half2*)(bd + j * 4) = __floats2half2_rn(pv[2 * j], pv[2 * j + 1]);
    };

    auto compute = [&](int buf) {
        uint32_t a_base = smem_u32(As[buf]) +
            (uint32_t)((wm * 64 + (lid & 15)) * RS + (lid >> 4) * 16);
        uint32_t b_base = smem_u32(Bs[buf]) +
            (uint32_t)((wn * 32 + (lid & 7) + ((lid >> 4) & 1) * 8) * RS +
                       ((lid >> 3) & 1) * 16);
#pragma unroll
        for (int st = 0; st < 2; st++) {
            uint32_t af[4][4], bf[2][4];
#pragma unroll
            for (int mt = 0; mt < 4; mt++)
                ldsm_x4(af[mt], a_base + mt * 16 * RS + st * 32);
#pragma unroll
            for (int bt = 0; bt < 2; bt++)
                ldsm_x4(bf[bt], b_base + bt * 16 * RS + st * 32);
#pragma unroll
            for (int mt = 0; mt < 4; mt++)
#pragma unroll
                for (int nt = 0; nt < 4; nt++) {
                    int bt = nt >> 1, pr = nt & 1;
                    mma_f16(acc[mt][nt], af[mt], bf[bt][pr * 2], bf[bt][pr * 2 + 1]);
                }
        }
    };

    gload(0);
    sstore(0);
    __syncthreads();
    for (int ch = 0; ch < 72; ch++) {
        int cur = ch & 1;
        if (ch < 71) gload(ch + 1);
        compute(cur);
        if (ch < 71) sstore(cur ^ 1);
        __syncthreads();
    }

    // epilogue: BN + ReLU
    int prow = y * 256 + x0 + wn * 32 + (lid & 3) * 2;
#pragma unroll
    for (int mt = 0; mt < 4; mt++) {
        int co0 = wm * 64 + mt * 16 + (lid >> 2);
        float sc0 = ssc[co0],     bi0 = sbi[co0];
        float sc1 = ssc[co0 + 8], bi1 = sbi[co0 + 8];
        float* hp0 = d_h + (((b << 7) + co0) << 16) + prow;
        float* hp1 = hp0 + (8 << 16);
#pragma unroll
        for (int nt = 0; nt < 4; nt++) {
            hp0[nt * 8]     = fmaxf(fmaf(acc[mt][nt][0], sc0, bi0), 0.f);
            hp0[nt * 8 + 1] = fmaxf(fmaf(acc[mt][nt][1], sc0, bi0), 0.f);
            hp1[nt * 8]     = fmaxf(fmaf(acc[mt][nt][2], sc1, bi1), 0.f);
            hp1[nt * 8 + 1] = fmaxf(fmaf(acc[mt][nt][3], sc1, bi1), 0.f);
        }
    }
}

// ---------------- 4: conv2 (3x3 128->9) fp16 mma + sigmoid ------------------
// CTA: M=128 px x N=16 co(pad) ; K=1152 in 36 chunks of 32 (tap-major -> L1 reuse)
__global__ void __launch_bounds__(256, 2)
conv2_mma(const float* __restrict__ bg2) {
    __shared__ __align__(16) char Ah[2][128 * RS];
    __shared__ __align__(16) char Bw[2][16 * RS];
    __shared__ float sb[16];

    const int tid = threadIdx.x;
    const int lid = tid & 31;
    const int wid = tid >> 5;           // m block (16 px each)
    const int b  = blockIdx.y;
    const int y  = blockIdx.x >> 1;
    const int x0 = (blockIdx.x & 1) << 7;
    const int col  = tid & 127;
    const int half = tid >> 7;

    if (tid < 16) sb[tid] = (tid < 9) ? bg2[tid] : 0.f;

    float acc[2][4];
#pragma unroll
    for (int i = 0; i < 2; i++)
#pragma unroll
        for (int c = 0; c < 4; c++) acc[i][c] = 0.f;

    float pv[16];
    uint32_t pw;

    auto gload = [&](int ch) {
        pw = ((const uint32_t*)(d_W2h + ch * 512))[tid & 255];
        int tap = ch >> 2;
        int ci0 = (ch & 3) << 5;
        int dy = tap / 3 - 1, dx = tap % 3 - 1;
        int yy = y + dy;
        int xx = x0 + dx + col;
        bool inb = ((unsigned)yy < 256u) && ((unsigned)xx < 256u);
        const float* hp = d_h + (((long)((b << 7) + ci0 + (half << 4))) << 16) + yy * 256 + xx;
#pragma unroll
        for (int i = 0; i < 16; i++)
            pv[i] = inb ? hp[i << 16] : 0.f;
    };

    auto sstore = [&](int buf) {
        char* ad = Ah[buf] + col * RS + half * 32;
#pragma unroll
        for (int j = 0; j < 8; j++)
            *(__half2*)(ad + j * 4) = __floats2half2_rn(pv[2 * j], pv[2 * j + 1]);
        // Bw: uint t covers co = t>>4, kpair = t&15
        *(uint32_t*)(Bw[buf] + (tid >> 4) * RS + (tid & 15) * 4) = pw;
    };

    auto compute = [&](int buf) {
        uint32_t a_base = smem_u32(Ah[buf]) +
            (uint32_t)((wid * 16 + (lid & 15)) * RS + (lid >> 4) * 16);
        uint32_t b_base = smem_u32(Bw[buf]) +
            (uint32_t)(((lid & 7) + ((lid >> 4) & 1) * 8) * RS + ((lid >> 3) & 1) * 16);
#pragma unroll
        for (int st = 0; st < 2; st++) {
            uint32_t af[4], bf[4];
            ldsm_x4(af, a_base + st * 32);
            ldsm_x4(bf, b_base + st * 32);
            mma_f16(acc[0], af, bf[0], bf[1]);
            mma_f16(acc[1], af, bf[2], bf[3]);
        }
    };

    gload(0);
    sstore(0);
    __syncthreads();
    for (int ch = 0; ch < 36; ch++) {
        int cur = ch & 1;
        if (ch < 35) gload(ch + 1);
        compute(cur);
        if (ch < 35) sstore(cur ^ 1);
        __syncthreads();
    }

    // epilogue: bias + sigmoid ; D[px][co], store co<9
    int px0 = wid * 16 + (lid >> 2);
    int cb  = (lid & 3) * 2;
    int pbase = y * 256 + x0;
#pragma unroll
    for (int nt = 0; nt < 2; nt++) {
#pragma unroll
        for (int c = 0; c < 4; c++) {
            int co = nt * 8 + cb + (c & 1);
            int px = px0 + (c >> 1) * 8;
            if (co < 9) {
                float g = acc[nt][c] + sb[co];
                float s = 1.f / (1.f + __expf(-g));
                d_gates[((b * 9 + co) << 16) + pbase + px] = s;
            }
        }
    }
}

// ---------------- 5: gated propagation --------------------------------------
__global__ void __launch_bounds__(256) prop_kernel(float* __restrict__ outp, int which) {
    const int dys[9] = {-1, -1, 0, 1, 1,  1,  0, -1, 0};
    const int dxs[9] = { 0,  1, 1, 1, 0, -1, -1, -1, 0};
    int pix = blockIdx.x * 256 + threadIdx.x;
    int b = pix >> 16, hw = pix & 65535;
    int y = hw >> 8, x = hw & 255;
    const float* rin  = which ? d_r1 : d_r0;
    float*       rout = which ? outp : d_r1;

    float deg = 0.f, agg = 0.f;
#pragma unroll
    for (int d = 0; d < 9; d++) {
        float gv = d_gates[((b * 9 + d) << 16) + hw];
        deg += gv;
        int ny = y - dys[d];
        int nx = x - dxs[d];
        float nb = 0.f;
        if ((unsigned)ny < 256u && (unsigned)nx < 256u)
            nb = rin[(b << 16) + (ny << 8) + nx];
        agg = fmaf(gv, nb, agg);
    }
    float rn = 0.3f * rin[pix] + 0.7f * (agg / (deg + 1e-6f));
    if (which) rn = fminf(fmaxf(rn, 0.f), 1.f);
    rout[pix] = rn;
}

// ---------------- launch ----------------------------------------------------
extern "C" void kernel_launch(void* const* d_in, const int* in_sizes, int n_in,
                              void* d_out, int out_size) {
    const float* x        = (const float*)d_in[0];
    const float* y        = (const float*)d_in[1];
    const float* Wx       = (const float*)d_in[2];
    const float* Wy       = (const float*)d_in[3];
    const float* Wg1      = (const float*)d_in[4];
    const float* bn_gamma = (const float*)d_in[5];
    const float* bn_beta  = (const float*)d_in[6];
    const float* bn_mean  = (const float*)d_in[7];
    const float* bn_var   = (const float*)d_in[8];
    const float* Wg2      = (const float*)d_in[9];
    const float* bg2      = (const float*)d_in[10];
    float* out = (float*)d_out;

    prep_w1<<<(72 * 4096 + 255) / 256, 256>>>(Wg1);
    prep_w2<<<(36 * 512 + 255) / 256, 256>>>(Wg2);
    embed_kernel<<<2048, 256>>>(x, Wx, 0);
    embed_kernel<<<2048, 256>>>(y, Wy, 1);
    r0_kernel<<<2048, 256>>>();
    conv1_mma<<<dim3(512, BATCH), 256>>>(bn_gamma, bn_beta, bn_mean, bn_var);
    conv2_mma<<<dim3(512, BATCH), 256>>>(bg2);
    prop_kernel<<<2048, 256>>>(out, 0);
    prop_kernel<<<2048, 256>>>(out, 1);
}

// round 13
// speedup vs baseline: 1.5130x; 1.5130x over previous
#include <cuda_runtime.h>
#include <math.h>
#include <cstdint>

typedef unsigned long long ull;

// ---------------- problem constants ----------------
#define BATCH 8
#define HWP   65536
#define G2    128
#define DD    9

// ---------------- scratch ----------------------------------------------------
__device__ __align__(16) float d_xemb[BATCH * 64 * HWP];
__device__ __align__(16) float d_yemb[BATCH * 64 * HWP];
__device__ __align__(16) float d_h   [BATCH * G2 * HWP];
__device__ __align__(16) float d_gates[BATCH * DD * HWP];
__device__ __align__(16) float d_r0  [BATCH * HWP];
__device__ __align__(16) float d_r1  [BATCH * HWP];
__device__ __align__(16) float d_WtA [144 * 2048];     // [chunk][co][kk] tf32 bits

// ---------------- helpers ----------------------------------------------------
__device__ __forceinline__ uint32_t smem_u32(const void* p) {
    uint32_t a;
    asm("{ .reg .u64 t; cvta.to.shared.u64 t, %1; cvt.u32.u64 %0, t; }" : "=r"(a) : "l"(p));
    return a;
}
__device__ __forceinline__ ull ffma2(ull a, ull b, ull c) {
    ull d; asm("fma.rn.f32x2 %0, %1, %2, %3;" : "=l"(d) : "l"(a), "l"(b), "l"(c)); return d;
}
__device__ __forceinline__ ull pack2(float a) {
    ull d; asm("mov.b64 %0, {%1, %1};" : "=l"(d) : "f"(a)); return d;
}
__device__ __forceinline__ uint32_t to_tf32(float f) {
    uint32_t u; asm("cvt.rna.tf32.f32 %0, %1;" : "=r"(u) : "f"(f)); return u;
}
__device__ __forceinline__ void ldsm_x4(uint32_t& r0, uint32_t& r1, uint32_t& r2, uint32_t& r3,
                                        uint32_t addr) {
    asm volatile("ldmatrix.sync.aligned.m8n8.x4.shared.b16 {%0,%1,%2,%3}, [%4];"
                 : "=r"(r0), "=r"(r1), "=r"(r2), "=r"(r3) : "r"(addr));
}
__device__ __forceinline__ void mma_tf32(float& d0, float& d1, float& d2, float& d3,
                                         uint32_t a0, uint32_t a1, uint32_t a2, uint32_t a3,
                                         uint32_t b0, uint32_t b1) {
    asm volatile("mma.sync.aligned.m16n8k8.row.col.f32.tf32.tf32.f32 "
                 "{%0,%1,%2,%3}, {%4,%5,%6,%7}, {%8,%9}, {%0,%1,%2,%3};"
                 : "+f"(d0), "+f"(d1), "+f"(d2), "+f"(d3)
                 : "r"(a0), "r"(a1), "r"(a2), "r"(a3), "r"(b0), "r"(b1));
}

// ---------------- 0: Wg1 -> tf32 tiles [ch][co][kk], k = ch*16+kk -----------
// global k = tap*256 + ci256, ci256 = (ch&15)*16 + kk, tap = ch>>4
__global__ void prep_w_tc(const float* __restrict__ Wg1) {
    int i = blockIdx.x * 256 + threadIdx.x;
    if (i >= 144 * 2048) return;
    int ch = i >> 11;
    int r  = i & 2047;
    int co = r >> 4;
    int kk = r & 15;
    int tap   = ch >> 4;
    int ci256 = ((ch & 15) << 4) + kk;
    float w = Wg1[co * 2304 + ci256 * 9 + tap];
    ((uint32_t*)d_WtA)[i] = to_tf32(w);
}

// ---------------- 1: 1x1 conv + L2 normalize --------------------------------
__global__ void __launch_bounds__(256)
embed_kernel(const float* __restrict__ in, const float* __restrict__ w, int which) {
    __shared__ float ws[64 * 64];
    int tid = threadIdx.x;
    for (int i = tid; i < 4096; i += 256) {
        int e = i >> 6, ci = i & 63;
        ws[ci * 64 + e] = w[i];
    }
    __syncthreads();
    int pix = blockIdx.x * 256 + tid;
    int b = pix >> 16, hw = pix & 65535;
    const float* ip = in + (b << 22) + hw;
    float acc[64];
#pragma unroll
    for (int e = 0; e < 64; e++) acc[e] = 0.f;
#pragma unroll 4
    for (int ci = 0; ci < 64; ci++) {
        float v = ip[ci << 16];
        const float4* wp = (const float4*)(ws + (ci << 6));
#pragma unroll
        for (int q = 0; q < 16; q++) {
            float4 w4 = wp[q];
            acc[4*q+0] = fmaf(w4.x, v, acc[4*q+0]);
            acc[4*q+1] = fmaf(w4.y, v, acc[4*q+1]);
            acc[4*q+2] = fmaf(w4.z, v, acc[4*q+2]);
            acc[4*q+3] = fmaf(w4.w, v, acc[4*q+3]);
        }
    }
    float ss = 0.f;
#pragma unroll
    for (int e = 0; e < 64; e++) ss = fmaf(acc[e], acc[e], ss);
    float inv = 1.f / (sqrtf(ss) + 1e-6f);
    float* op = (which ? d_yemb : d_xemb) + (b << 22) + hw;
#pragma unroll
    for (int e = 0; e < 64; e++) op[e << 16] = acc[e] * inv;
}

// ---------------- 2: r0 -----------------------------------------------------
__global__ void __launch_bounds__(256) r0_kernel() {
    int pix = blockIdx.x * 256 + threadIdx.x;
    int b = pix >> 16, hw = pix & 65535;
    const float* xp = d_xemb + (b << 22) + hw;
    const float* yp = d_yemb + (b << 22) + hw;
    float s = 0.f;
#pragma unroll 8
    for (int e = 0; e < 64; e++) s = fmaf(xp[e << 16], yp[e << 16], s);
    d_r0[pix] = (s + 1.f) * 0.5f;
}

// ---------------- 3: conv1 via mma.sync tf32 implicit GEMM ------------------
// CTA: 128 co x 128 px, K=2304 in 144 chunks of 16.
// A smem [co][kk] rows of 16 tf32, row stride 20 floats (80B).
// B smem [px][kk] rows, same stride. ldmatrix.x4.b16 fragment loads.
// OCCUPANCY 2: the single change vs the 4217us baseline.
__global__ void __launch_bounds__(256, 2)
conv1_mma(const float* __restrict__ bn_g, const float* __restrict__ bn_b,
          const float* __restrict__ bn_m, const float* __restrict__ bn_v) {
    __shared__ __align__(16) float As[2][2560];   // 128 rows * 20
    __shared__ __align__(16) float Bs[2][2560];
    __shared__ float ssc[128], sbi[128];

    const int tid = threadIdx.x;
    const int lid = tid & 31;
    const int wid = tid >> 5;
    const int wm = wid >> 2;            // 0..1  (m block of 64)
    const int wn = wid & 3;             // 0..3  (n block of 32)
    const int b  = blockIdx.y;
    const int y  = blockIdx.x >> 1;
    const int x0 = (blockIdx.x & 1) << 7;

    if (tid < 128) {
        float iv = rsqrtf(bn_v[tid] + 1e-5f);
        float sc = bn_g[tid] * iv;
        ssc[tid] = sc;
        sbi[tid] = bn_b[tid] - bn_m[tid] * sc;
    }

    float acc[4][4][4];
#pragma unroll
    for (int i = 0; i < 4; i++)
#pragma unroll
        for (int j = 0; j < 4; j++)
#pragma unroll
            for (int c = 0; c < 4; c++) acc[i][j][c] = 0.f;

    // prefetch registers
    float4 pa[2];
    float  pvx[8], pvb[8];
    int    pgrp = 0;

    auto gload = [&](int ch) {
        const float4* asrc = (const float4*)(d_WtA + ch * 2048);
        pa[0] = asrc[tid];
        pa[1] = asrc[tid + 256];
        int tap = ch >> 4;
        int ci0 = (ch & 15) << 4;
        pgrp    = ci0 >> 6;              // gi group 0..3
        int c0  = ci0 & 63;              // channel base within embedding
        int dy = tap / 3 - 1, dx = tap % 3 - 1;
        int yy = y + dy;
        bool rowok = ((unsigned)yy < 256u);
        bool needx = (pgrp != 1), needy = (pgrp != 0);
#pragma unroll
        for (int i = 0; i < 8; i++) {
            int idx = tid + (i << 8);
            int rk  = idx >> 7;          // kk 0..15
            int col = idx & 127;         // pixel
            int xx  = x0 + dx + col;
            bool inb = rowok && ((unsigned)xx < 256u);
            int base = (((b << 6) + c0 + rk) << 16) + yy * 256 + xx;
            pvx[i] = (needx && inb) ? d_xemb[base] : 0.f;
            pvb[i] = (needy && inb) ? d_yemb[base] : 0.f;
        }
    };

    auto sstore = [&](int buf) {
        // A: 512 float4; thread t covers (co = t>>2, k4 = t&3)
        {
            int t0 = tid;
            ((float4*)(As[buf] + (t0 >> 2) * 20 + (t0 & 3) * 4))[0] = pa[0];
            int t1 = tid + 256;
            ((float4*)(As[buf] + (t1 >> 2) * 20 + (t1 & 3) * 4))[0] = pa[1];
        }
#pragma unroll
        for (int i = 0; i < 8; i++) {
            int idx = tid + (i << 8);
            int rk  = idx >> 7;
            int col = idx & 127;
            float v;
            if      (pgrp == 0) v = pvx[i];
            else if (pgrp == 1) v = pvb[i];
            else if (pgrp == 2) v = fabsf(pvx[i] - pvb[i]);
            else                v = pvx[i] * pvb[i];
            ((uint32_t*)Bs[buf])[col * 20 + rk] = to_tf32(v);
        }
    };

    auto compute = [&](int buf) {
        uint32_t As_b = smem_u32(As[buf]);
        uint32_t Bs_b = smem_u32(Bs[buf]);
        // ldmatrix per-thread row addresses
        uint32_t a_base = As_b + (uint32_t)((wm * 64 + (lid & 7) + ((lid >> 3) & 1) * 8) * 80
                                            + ((lid >> 4) & 1) * 16);
        uint32_t b_base = Bs_b + (uint32_t)((wn * 32 + (lid & 7) + ((lid >> 4) & 1) * 8) * 80
                                            + ((lid >> 3) & 1) * 16);
#pragma unroll
        for (int k8 = 0; k8 < 2; k8++) {
            uint32_t af[4][4], bf[2][4];
#pragma unroll
            for (int mt = 0; mt < 4; mt++)
                ldsm_x4(af[mt][0], af[mt][1], af[mt][2], af[mt][3],
                        a_base + k8 * 32 + mt * 1280);
#pragma unroll
            for (int bt = 0; bt < 2; bt++)
                ldsm_x4(bf[bt][0], bf[bt][1], bf[bt][2], bf[bt][3],
                        b_base + k8 * 32 + bt * 1280);
#pragma unroll
            for (int mt = 0; mt < 4; mt++)
#pragma unroll
                for (int nt = 0; nt < 4; nt++) {
                    int bt = nt >> 1, pr = nt & 1;
                    mma_tf32(acc[mt][nt][0], acc[mt][nt][1], acc[mt][nt][2], acc[mt][nt][3],
                             af[mt][0], af[mt][1], af[mt][2], af[mt][3],
                             bf[bt][pr * 2], bf[bt][pr * 2 + 1]);
                }
        }
    };

    gload(0);
    sstore(0);
    __syncthreads();
    for (int ch = 0; ch < 144; ch++) {
        int cur = ch & 1;
        if (ch < 143) gload(ch + 1);
        compute(cur);
        if (ch < 143) sstore(cur ^ 1);
        __syncthreads();
    }

    // epilogue: BN + ReLU, direct fragment stores (2 consecutive floats/lane)
    int prow = y * 256 + x0 + wn * 32 + (lid & 3) * 2;
#pragma unroll
    for (int mt = 0; mt < 4; mt++) {
        int co0 = wm * 64 + mt * 16 + (lid >> 2);
        float sc0 = ssc[co0],     bi0 = sbi[co0];
        float sc1 = ssc[co0 + 8], bi1 = sbi[co0 + 8];
        float* hp0 = d_h + (((b << 7) + co0) << 16) + prow;
        float* hp1 = hp0 + (8 << 16);
#pragma unroll
        for (int nt = 0; nt < 4; nt++) {
            hp0[nt * 8]     = fmaxf(fmaf(acc[mt][nt][0], sc0, bi0), 0.f);
            hp0[nt * 8 + 1] = fmaxf(fmaf(acc[mt][nt][1], sc0, bi0), 0.f);
            hp1[nt * 8]     = fmaxf(fmaf(acc[mt][nt][2], sc1, bi1), 0.f);
            hp1[nt * 8 + 1] = fmaxf(fmaf(acc[mt][nt][3], sc1, bi1), 0.f);
        }
    }
}

// ---------------- 4: conv2 (3x3, 128->9) + bias + sigmoid, f32x2 ------------
__global__ void __launch_bounds__(256)
conv2_kernel(const float* __restrict__ Wg2, const float* __restrict__ bg2) {
    __shared__ float ht[8][324];
    __shared__ __align__(8) float ws2[720];   // [(cc*9+tap)][10] slots co0..8+pad
    int tid = threadIdx.x;
    int px = tid & 15, py = tid >> 4;
    int x0 = blockIdx.x * 16, y0 = blockIdx.y * 16;
    int x = x0 + px, y = y0 + py;
    int b = blockIdx.z;

    ull a01 = 0, a23 = 0, a45 = 0, a67 = 0, a89 = 0;

    for (int ci0 = 0; ci0 < 128; ci0 += 8) {
        __syncthreads();
        for (int i = tid; i < 2592; i += 256) {
            int ci = i / 324;
            int j  = i - ci * 324;
            int ry = j / 18;
            int rx = j - ry * 18;
            int gy = y0 + ry - 1, gx = x0 + rx - 1;
            float v = 0.f;
            if ((unsigned)gy < 256u && (unsigned)gx < 256u)
                v = d_h[(((b << 7) + ci0 + ci) << 16) + gy * 256 + gx];
            ht[ci][j] = v;
        }
        for (int i = tid; i < 720; i += 256) {
            int slot = i % 10, r = i / 10;
            int cc = r / 9, tap = r % 9;
            ws2[i] = (slot < 9) ? Wg2[slot * 1152 + (ci0 + cc) * 9 + tap] : 0.f;
        }
        __syncthreads();
#pragma unroll
        for (int cc = 0; cc < 8; cc++) {
#pragma unroll
            for (int tap = 0; tap < 9; tap++) {
                int dy = tap / 3, dx = tap % 3;
                float t = ht[cc][(py + dy) * 18 + px + dx];
                ull tp = pack2(t);
                const ull* wp = (const ull*)(ws2 + (cc * 9 + tap) * 10);
                a01 = ffma2(tp, wp[0], a01);
                a23 = ffma2(tp, wp[1], a23);
                a45 = ffma2(tp, wp[2], a45);
                a67 = ffma2(tp, wp[3], a67);
                a89 = ffma2(tp, wp[4], a89);
            }
        }
    }
    float acc[9];
    acc[0] = __uint_as_float((unsigned)a01); acc[1] = __uint_as_float((unsigned)(a01 >> 32));
    acc[2] = __uint_as_float((unsigned)a23); acc[3] = __uint_as_float((unsigned)(a23 >> 32));
    acc[4] = __uint_as_float((unsigned)a45); acc[5] = __uint_as_float((unsigned)(a45 >> 32));
    acc[6] = __uint_as_float((unsigned)a67); acc[7] = __uint_as_float((unsigned)(a67 >> 32));
    acc[8] = __uint_as_float((unsigned)a89);
#pragma unroll
    for (int co = 0; co < 9; co++) {
        float g = acc[co] + bg2[co];
        float s = 1.f / (1.f + __expf(-g));
        d_gates[((b * 9 + co) << 16) + y * 256 + x] = s;
    }
}

// ---------------- 5: gated propagation --------------------------------------
__global__ void __launch_bounds__(256) prop_kernel(float* __restrict__ outp, int which) {
    const int dys[9] = {-1, -1, 0, 1, 1,  1,  0, -1, 0};
    const int dxs[9] = { 0,  1, 1, 1, 0, -1, -1, -1, 0};
    int pix = blockIdx.x * 256 + threadIdx.x;
    int b = pix >> 16, hw = pix & 65535;
    int y = hw >> 8, x = hw & 255;
    const float* rin  = which ? d_r1 : d_r0;
    float*       rout = which ? outp : d_r1;

    float deg = 0.f, agg = 0.f;
#pragma unroll
    for (int d = 0; d < 9; d++) {
        float gv = d_gates[((b * 9 + d) << 16) + hw];
        deg += gv;
        int ny = y - dys[d];
        int nx = x - dxs[d];
        float nb = 0.f;
        if ((unsigned)ny < 256u && (unsigned)nx < 256u)
            nb = rin[(b << 16) + (ny << 8) + nx];
        agg = fmaf(gv, nb, agg);
    }
    float rn = 0.3f * rin[pix] + 0.7f * (agg / (deg + 1e-6f));
    if (which) rn = fminf(fmaxf(rn, 0.f), 1.f);
    rout[pix] = rn;
}

// ---------------- launch ----------------------------------------------------
extern "C" void kernel_launch(void* const* d_in, const int* in_sizes, int n_in,
                              void* d_out, int out_size) {
    const float* x        = (const float*)d_in[0];
    const float* y        = (const float*)d_in[1];
    const float* Wx       = (const float*)d_in[2];
    const float* Wy       = (const float*)d_in[3];
    const float* Wg1      = (const float*)d_in[4];
    const float* bn_gamma = (const float*)d_in[5];
    const float* bn_beta  = (const float*)d_in[6];
    const float* bn_mean  = (const float*)d_in[7];
    const float* bn_var   = (const float*)d_in[8];
    const float* Wg2      = (const float*)d_in[9];
    const float* bg2      = (const float*)d_in[10];
    float* out = (float*)d_out;

    prep_w_tc<<<(144 * 2048 + 255) / 256, 256>>>(Wg1);
    embed_kernel<<<2048, 256>>>(x, Wx, 0);
    embed_kernel<<<2048, 256>>>(y, Wy, 1);
    r0_kernel<<<2048, 256>>>();
    conv1_mma<<<dim3(512, BATCH), 256>>>(bn_gamma, bn_beta, bn_mean, bn_var);
    conv2_kernel<<<dim3(16, 16, BATCH), 256>>>(Wg2, bg2);
    prop_kernel<<<2048, 256>>>(out, 0);
    prop_kernel<<<2048, 256>>>(out, 1);
}